// round 6
// baseline (speedup 1.0000x reference)
#include <cuda_runtime.h>
#include <cuda_bf16.h>
#include <stdint.h>
#include <math.h>

// ---------------- Problem constants ----------------
#define BATCH 512
#define C1 256
#define ROUTES 1152
#define NCAPS 10
#define CAPDIM 16
#define M2 (BATCH*36)     // 18432
#define K2 20736          // 256*81
#define N2 256
#define FLAT 9216

// ---------------- Device scratch ----------------
__device__ __align__(16) uint32_t g_x1p[BATCH*C1*20*20];     // packed bf16 hi|lo (210MB)
__device__ __align__(16) uint32_t g_bp[(size_t)N2*K2];       // packed pc_w (21MB)
__device__ __align__(16) int      g_kofft[K2];
__device__ __align__(16) float g_c2[BATCH*FLAT];
__device__ __align__(16) float g_u[BATCH*FLAT];
__device__ __align__(16) float g_uhat[(size_t)BATCH*ROUTES*NCAPS*CAPDIM];
__device__ __align__(16) float g_bij[ROUTES*NCAPS];
__device__ __align__(16) float g_cij[ROUTES*NCAPS];
__device__ __align__(16) float g_v[BATCH*NCAPS*CAPDIM];
__device__ int   g_best[BATCH];
__device__ __align__(16) float g_h1[BATCH*512];
__device__ __align__(16) float g_h2[BATCH*1024];

// ---------------- pack helper: fp32 -> (bf16 hi) | (bf16 lo)<<16 ----------------
__device__ __forceinline__ uint32_t pack_split(float x) {
    __nv_bfloat16 h = __float2bfloat16(x);
    __nv_bfloat16 l = __float2bfloat16(x - __bfloat162float(h));
    return (uint32_t)__bfloat16_as_ushort(h) | ((uint32_t)__bfloat16_as_ushort(l) << 16);
}

// ---------------- B pre-split ----------------
__global__ void bsplit_kernel(const float* __restrict__ w, uint32_t* __restrict__ bp) {
    int i = blockIdx.x * 1024 + threadIdx.x;
    if (i < N2 * K2) bp[i] = pack_split(w[i]);
}

// ---------------- im2col offset table ----------------
__global__ void kofft_kernel(int* __restrict__ tab) {
    int k = blockIdx.x * 256 + threadIdx.x;
    if (k >= K2) return;
    int ci = k / 81, rem = k - ci * 81;
    int ky = rem / 9, kx = rem - ky * 9;
    tab[k] = ci * 400 + ky * 20 + kx;
}

// ---------------- Conv1: 1->256, 9x9, stride1, relu -> packed split ----------------
__global__ void conv1_kernel(const float* __restrict__ img, const float* __restrict__ w,
                             const float* __restrict__ bias, uint32_t* __restrict__ x1p) {
    __shared__ float ism[784];
    __shared__ float wsm[32 * 81];
    int b = blockIdx.x, g = blockIdx.y;
    for (int i = threadIdx.x; i < 784; i += 256) ism[i] = img[b * 784 + i];
    for (int i = threadIdx.x; i < 2592; i += 256) wsm[i] = w[g * 2592 + i];
    __syncthreads();
    for (int idx = threadIdx.x; idx < 32 * 400; idx += 256) {
        int cl = idx / 400, pix = idx - cl * 400;
        int y = pix / 20, x = pix - y * 20;
        const float* wp = &wsm[cl * 81];
        float acc = bias[g * 32 + cl];
        #pragma unroll
        for (int ky = 0; ky < 9; ky++) {
            const float* irow = &ism[(y + ky) * 28 + x];
            #pragma unroll
            for (int kx = 0; kx < 9; kx++)
                acc += irow[kx] * wp[ky * 9 + kx];
        }
        x1p[(size_t)b * 102400 + (size_t)(g * 32 + cl) * 400 + pix] = pack_split(fmaxf(acc, 0.f));
    }
}

// ---------------- Conv2 implicit GEMM via split-bf16 tensor-core MMA ----------------
#define BK 16
#define LDS_PAD 24

__device__ __forceinline__ void mma_bf16(float& c0, float& c1, float& c2, float& c3,
                                         uint32_t a0, uint32_t a1, uint32_t a2, uint32_t a3,
                                         uint32_t b0, uint32_t b1) {
    asm volatile(
        "mma.sync.aligned.m16n8k16.row.col.f32.bf16.bf16.f32 "
        "{%0,%1,%2,%3}, {%4,%5,%6,%7}, {%8,%9}, {%0,%1,%2,%3};\n"
        : "+f"(c0), "+f"(c1), "+f"(c2), "+f"(c3)
        : "r"(a0), "r"(a1), "r"(a2), "r"(a3), "r"(b0), "r"(b1));
}

__global__ __launch_bounds__(256, 1)
void conv2_mma_kernel(const uint32_t* __restrict__ x1p, const uint32_t* __restrict__ bp,
                      const int* __restrict__ kofft,
                      const float* __restrict__ bias, float* __restrict__ out) {
    __shared__ __align__(16) __nv_bfloat16 AsH[2][128 * LDS_PAD];
    __shared__ __align__(16) __nv_bfloat16 AsL[2][128 * LDS_PAD];
    __shared__ __align__(16) __nv_bfloat16 BsH[2][128 * LDS_PAD];
    __shared__ __align__(16) __nv_bfloat16 BsL[2][128 * LDS_PAD];

    const int t = threadIdx.x;
    const int m0 = blockIdx.y * 128;
    const int n0 = blockIdx.x * 128;

    // loader mapping: row = t>>1 (0..127), k-half = (t&1)*8
    const int lr  = t >> 1;
    const int lkh = (t & 1) * 8;

    const int mg = m0 + lr;
    const int bb = mg / 36;
    const int ss = mg - bb * 36;
    const int oy = ss / 6, ox = ss - oy * 6;
    const uint32_t* abase = x1p + (size_t)bb * 102400 + oy * 40 + ox * 2;
    const uint32_t* bbase = bp + (size_t)(n0 + lr) * K2;
    const int sa = lr * LDS_PAD + lkh;          // bf16 elem offset; *2 = byte (16B aligned)

    // compute mapping
    const int wid = t >> 5;
    const int wm = wid >> 2;
    const int wn = wid & 3;
    const int lane = t & 31;
    const int qr = lane >> 2;
    const int qc = (lane & 3) * 2;

    float acc[4][4][4];
    #pragma unroll
    for (int i = 0; i < 4; i++)
        #pragma unroll
        for (int j = 0; j < 4; j++)
            #pragma unroll
            for (int r = 0; r < 4; r++) acc[i][j][r] = 0.f;

    uint32_t av[8], bv[8];

    // prologue: load k-step 0
    {
        int kk = lkh;
        int4 o0 = *reinterpret_cast<const int4*>(kofft + kk);
        int4 o1 = *reinterpret_cast<const int4*>(kofft + kk + 4);
        av[0] = abase[o0.x]; av[1] = abase[o0.y]; av[2] = abase[o0.z]; av[3] = abase[o0.w];
        av[4] = abase[o1.x]; av[5] = abase[o1.y]; av[6] = abase[o1.z]; av[7] = abase[o1.w];
        uint4 u0 = *reinterpret_cast<const uint4*>(bbase + kk);
        uint4 u1 = *reinterpret_cast<const uint4*>(bbase + kk + 4);
        bv[0]=u0.x; bv[1]=u0.y; bv[2]=u0.z; bv[3]=u0.w;
        bv[4]=u1.x; bv[5]=u1.y; bv[6]=u1.z; bv[7]=u1.w;
        uint4 ah4, al4, bh4, bl4;
        ah4.x=__byte_perm(av[0],av[1],0x5410); ah4.y=__byte_perm(av[2],av[3],0x5410);
        ah4.z=__byte_perm(av[4],av[5],0x5410); ah4.w=__byte_perm(av[6],av[7],0x5410);
        al4.x=__byte_perm(av[0],av[1],0x7632); al4.y=__byte_perm(av[2],av[3],0x7632);
        al4.z=__byte_perm(av[4],av[5],0x7632); al4.w=__byte_perm(av[6],av[7],0x7632);
        bh4.x=__byte_perm(bv[0],bv[1],0x5410); bh4.y=__byte_perm(bv[2],bv[3],0x5410);
        bh4.z=__byte_perm(bv[4],bv[5],0x5410); bh4.w=__byte_perm(bv[6],bv[7],0x5410);
        bl4.x=__byte_perm(bv[0],bv[1],0x7632); bl4.y=__byte_perm(bv[2],bv[3],0x7632);
        bl4.z=__byte_perm(bv[4],bv[5],0x7632); bl4.w=__byte_perm(bv[6],bv[7],0x7632);
        *reinterpret_cast<uint4*>(&AsH[0][sa]) = ah4;
        *reinterpret_cast<uint4*>(&AsL[0][sa]) = al4;
        *reinterpret_cast<uint4*>(&BsH[0][sa]) = bh4;
        *reinterpret_cast<uint4*>(&BsL[0][sa]) = bl4;
    }
    __syncthreads();

    const int NSTEP = K2 / BK;   // 1296
    for (int s = 0; s < NSTEP; s++) {
        const int cur = s & 1;
        const bool more = (s + 1 < NSTEP);
        // prefetch next k-step into registers
        if (more) {
            int kk = (s + 1) * BK + lkh;
            int4 o0 = *reinterpret_cast<const int4*>(kofft + kk);
            int4 o1 = *reinterpret_cast<const int4*>(kofft + kk + 4);
            av[0] = abase[o0.x]; av[1] = abase[o0.y]; av[2] = abase[o0.z]; av[3] = abase[o0.w];
            av[4] = abase[o1.x]; av[5] = abase[o1.y]; av[6] = abase[o1.z]; av[7] = abase[o1.w];
            uint4 u0 = *reinterpret_cast<const uint4*>(bbase + kk);
            uint4 u1 = *reinterpret_cast<const uint4*>(bbase + kk + 4);
            bv[0]=u0.x; bv[1]=u0.y; bv[2]=u0.z; bv[3]=u0.w;
            bv[4]=u1.x; bv[5]=u1.y; bv[6]=u1.z; bv[7]=u1.w;
        }

        // compute on stage `cur`
        {
            uint32_t ah[4][4], al[4][4], bh[4][2], bl[4][2];
            #pragma unroll
            for (int i = 0; i < 4; i++) {
                int r0 = (wm * 64 + i * 16 + qr) * LDS_PAD;
                int r8 = r0 + 8 * LDS_PAD;
                ah[i][0] = *reinterpret_cast<const uint32_t*>(&AsH[cur][r0 + qc]);
                ah[i][1] = *reinterpret_cast<const uint32_t*>(&AsH[cur][r8 + qc]);
                ah[i][2] = *reinterpret_cast<const uint32_t*>(&AsH[cur][r0 + qc + 8]);
                ah[i][3] = *reinterpret_cast<const uint32_t*>(&AsH[cur][r8 + qc + 8]);
                al[i][0] = *reinterpret_cast<const uint32_t*>(&AsL[cur][r0 + qc]);
                al[i][1] = *reinterpret_cast<const uint32_t*>(&AsL[cur][r8 + qc]);
                al[i][2] = *reinterpret_cast<const uint32_t*>(&AsL[cur][r0 + qc + 8]);
                al[i][3] = *reinterpret_cast<const uint32_t*>(&AsL[cur][r8 + qc + 8]);
            }
            #pragma unroll
            for (int j = 0; j < 4; j++) {
                int nr = (wn * 32 + j * 8 + qr) * LDS_PAD;
                bh[j][0] = *reinterpret_cast<const uint32_t*>(&BsH[cur][nr + qc]);
                bh[j][1] = *reinterpret_cast<const uint32_t*>(&BsH[cur][nr + qc + 8]);
                bl[j][0] = *reinterpret_cast<const uint32_t*>(&BsL[cur][nr + qc]);
                bl[j][1] = *reinterpret_cast<const uint32_t*>(&BsL[cur][nr + qc + 8]);
            }
            #pragma unroll
            for (int i = 0; i < 4; i++)
                #pragma unroll
                for (int j = 0; j < 4; j++) {
                    mma_bf16(acc[i][j][0], acc[i][j][1], acc[i][j][2], acc[i][j][3],
                             ah[i][0], ah[i][1], ah[i][2], ah[i][3], bh[j][0], bh[j][1]);
                    mma_bf16(acc[i][j][0], acc[i][j][1], acc[i][j][2], acc[i][j][3],
                             ah[i][0], ah[i][1], ah[i][2], ah[i][3], bl[j][0], bl[j][1]);
                    mma_bf16(acc[i][j][0], acc[i][j][1], acc[i][j][2], acc[i][j][3],
                             al[i][0], al[i][1], al[i][2], al[i][3], bh[j][0], bh[j][1]);
                }
        }

        // store prefetched regs into the other stage
        if (more) {
            int nxt = cur ^ 1;
            uint4 ah4, al4, bh4, bl4;
            ah4.x=__byte_perm(av[0],av[1],0x5410); ah4.y=__byte_perm(av[2],av[3],0x5410);
            ah4.z=__byte_perm(av[4],av[5],0x5410); ah4.w=__byte_perm(av[6],av[7],0x5410);
            al4.x=__byte_perm(av[0],av[1],0x7632); al4.y=__byte_perm(av[2],av[3],0x7632);
            al4.z=__byte_perm(av[4],av[5],0x7632); al4.w=__byte_perm(av[6],av[7],0x7632);
            bh4.x=__byte_perm(bv[0],bv[1],0x5410); bh4.y=__byte_perm(bv[2],bv[3],0x5410);
            bh4.z=__byte_perm(bv[4],bv[5],0x5410); bh4.w=__byte_perm(bv[6],bv[7],0x5410);
            bl4.x=__byte_perm(bv[0],bv[1],0x7632); bl4.y=__byte_perm(bv[2],bv[3],0x7632);
            bl4.z=__byte_perm(bv[4],bv[5],0x7632); bl4.w=__byte_perm(bv[6],bv[7],0x7632);
            *reinterpret_cast<uint4*>(&AsH[nxt][sa]) = ah4;
            *reinterpret_cast<uint4*>(&AsL[nxt][sa]) = al4;
            *reinterpret_cast<uint4*>(&BsH[nxt][sa]) = bh4;
            *reinterpret_cast<uint4*>(&BsL[nxt][sa]) = bl4;
        }
        __syncthreads();
    }

    // epilogue: C[m][n] -> out[b*FLAT + n*36 + s] + bias[n]
    #pragma unroll
    for (int i = 0; i < 4; i++) {
        #pragma unroll
        for (int j = 0; j < 4; j++) {
            int r = m0 + wm * 64 + i * 16 + qr;
            int c = n0 + wn * 32 + j * 8 + qc;
            #pragma unroll
            for (int rr = 0; rr < 2; rr++) {
                int m = r + rr * 8;
                int b = m / 36, sidx = m - b * 36;
                float* op = out + (size_t)b * FLAT + sidx;
                op[(c + 0) * 36] = acc[i][j][rr * 2 + 0] + bias[c + 0];
                op[(c + 1) * 36] = acc[i][j][rr * 2 + 1] + bias[c + 1];
            }
        }
    }
}

// ---------------- Squash u ----------------
__global__ void squash_u_kernel(const float* __restrict__ c2, float* __restrict__ u) {
    int i = blockIdx.x * 256 + threadIdx.x;
    if (i >= BATCH * ROUTES) return;
    const float4* p = reinterpret_cast<const float4*>(c2 + (size_t)i * 8);
    float4 a = p[0], b = p[1];
    float sn = a.x*a.x + a.y*a.y + a.z*a.z + a.w*a.w
             + b.x*b.x + b.y*b.y + b.z*b.z + b.w*b.w + 1e-7f;
    float sc = sqrtf(sn) / (1.f + sn);
    float4 oa = make_float4(a.x*sc, a.y*sc, a.z*sc, a.w*sc);
    float4 ob = make_float4(b.x*sc, b.y*sc, b.z*sc, b.w*sc);
    float4* q = reinterpret_cast<float4*>(u + (size_t)i * 8);
    q[0] = oa; q[1] = ob;
}

// ---------------- u_hat ----------------
__global__ void uhat_kernel(const float* __restrict__ W, const float* __restrict__ u,
                            float* __restrict__ uhat) {
    __shared__ float Wsm[1280];
    __shared__ float usm[256];
    int r = blockIdx.x;
    int bg = blockIdx.y;
    for (int i = threadIdx.x; i < 1280; i += 256) Wsm[i] = W[(size_t)r * 1280 + i];
    {
        int i = threadIdx.x;
        int bb = bg * 32 + (i >> 3);
        usm[i] = u[(size_t)bb * FLAT + r * 8 + (i & 7)];
    }
    __syncthreads();
    for (int i = threadIdx.x; i < 5120; i += 256) {
        int bi = i / 160, ko = i - bi * 160;
        const float* wp = &Wsm[ko * 8];
        const float* up = &usm[bi * 8];
        float acc = 0.f;
        #pragma unroll
        for (int c = 0; c < 8; c++) acc += wp[c] * up[c];
        uhat[((size_t)(bg * 32 + bi) * ROUTES + r) * 160 + ko] = acc;
    }
}

// ---------------- Routing ----------------
__global__ void zero_bij_kernel(float* __restrict__ bij) {
    int i = blockIdx.x * 256 + threadIdx.x;
    if (i < ROUTES * NCAPS) bij[i] = 0.f;
}

__global__ void softmax_routes_kernel(const float* __restrict__ b, float* __restrict__ c) {
    int k = blockIdx.x;
    __shared__ float red[256];
    int tid = threadIdx.x;
    float m = -1e30f;
    for (int r = tid; r < ROUTES; r += 256) m = fmaxf(m, b[r * 10 + k]);
    red[tid] = m; __syncthreads();
    for (int s = 128; s > 0; s >>= 1) {
        if (tid < s) red[tid] = fmaxf(red[tid], red[tid + s]);
        __syncthreads();
    }
    m = red[0]; __syncthreads();
    float sum = 0.f;
    for (int r = tid; r < ROUTES; r += 256) sum += expf(b[r * 10 + k] - m);
    red[tid] = sum; __syncthreads();
    for (int s = 128; s > 0; s >>= 1) {
        if (tid < s) red[tid] += red[tid + s];
        __syncthreads();
    }
    float inv = 1.f / red[0];
    for (int r = tid; r < ROUTES; r += 256) c[r * 10 + k] = expf(b[r * 10 + k] - m) * inv;
}

__global__ void sv_kernel(const float* __restrict__ cij, const float* __restrict__ uhat,
                          float* __restrict__ v) {
    int b = blockIdx.x, k = blockIdx.y;
    int tid = threadIdx.x;
    float acc[16];
    #pragma unroll
    for (int o = 0; o < 16; o++) acc[o] = 0.f;
    for (int r = tid; r < ROUTES; r += 128) {
        float cc = cij[r * 10 + k];
        const float4* p = reinterpret_cast<const float4*>(uhat + ((size_t)(b * ROUTES + r) * 10 + k) * 16);
        float4 x0 = p[0], x1 = p[1], x2 = p[2], x3 = p[3];
        acc[0]  += cc * x0.x; acc[1]  += cc * x0.y; acc[2]  += cc * x0.z; acc[3]  += cc * x0.w;
        acc[4]  += cc * x1.x; acc[5]  += cc * x1.y; acc[6]  += cc * x1.z; acc[7]  += cc * x1.w;
        acc[8]  += cc * x2.x; acc[9]  += cc * x2.y; acc[10] += cc * x2.z; acc[11] += cc * x2.w;
        acc[12] += cc * x3.x; acc[13] += cc * x3.y; acc[14] += cc * x3.z; acc[15] += cc * x3.w;
    }
    __shared__ float red[128 * 16];
    #pragma unroll
    for (int o = 0; o < 16; o++) red[tid * 16 + o] = acc[o];
    __syncthreads();
    for (int s = 64; s > 0; s >>= 1) {
        if (tid < s) {
            #pragma unroll
            for (int o = 0; o < 16; o++) red[tid * 16 + o] += red[(tid + s) * 16 + o];
        }
        __syncthreads();
    }
    if (tid == 0) {
        float sn = 0.f;
        #pragma unroll
        for (int o = 0; o < 16; o++) sn += red[o] * red[o];
        float sc = sqrtf(sn) / (1.f + sn);
        #pragma unroll
        for (int o = 0; o < 16; o++) v[(b * 10 + k) * 16 + o] = red[o] * sc;
    }
}

__global__ void agree_kernel(const float* __restrict__ uhat, const float* __restrict__ v,
                             float* __restrict__ bij) {
    int r = blockIdx.x, k = blockIdx.y;
    int tid = threadIdx.x;
    __shared__ __align__(16) float vsm[BATCH * 16];
    __shared__ float red[256];
    for (int i = tid; i < BATCH * 16; i += 256) {
        int bb = i >> 4, o = i & 15;
        vsm[i] = v[(bb * 10 + k) * 16 + o];
    }
    __syncthreads();
    float acc = 0.f;
    for (int bb = tid; bb < BATCH; bb += 256) {
        const float4* p = reinterpret_cast<const float4*>(uhat + ((size_t)(bb * ROUTES + r) * 10 + k) * 16);
        const float4* q = reinterpret_cast<const float4*>(&vsm[bb * 16]);
        float4 a0 = p[0], a1 = p[1], a2 = p[2], a3 = p[3];
        float4 b0 = q[0], b1 = q[1], b2 = q[2], b3 = q[3];
        acc += a0.x*b0.x + a0.y*b0.y + a0.z*b0.z + a0.w*b0.w;
        acc += a1.x*b1.x + a1.y*b1.y + a1.z*b1.z + a1.w*b1.w;
        acc += a2.x*b2.x + a2.y*b2.y + a2.z*b2.z + a2.w*b2.w;
        acc += a3.x*b3.x + a3.y*b3.y + a3.z*b3.z + a3.w*b3.w;
    }
    red[tid] = acc; __syncthreads();
    for (int s = 128; s > 0; s >>= 1) {
        if (tid < s) red[tid] += red[tid + s];
        __syncthreads();
    }
    if (tid == 0) bij[r * 10 + k] += red[0] * (1.f / (float)BATCH);
}

// ---------------- Mask / argmax ----------------
__global__ void mask_kernel(const float* __restrict__ v, float* __restrict__ out_obj,
                            float* __restrict__ out_mask, int* __restrict__ best) {
    int b = blockIdx.x * blockDim.x + threadIdx.x;
    if (b >= BATCH) return;
    const float* vb = v + b * 160;
    float bestn = -1.f; int bi = 0;
    #pragma unroll
    for (int k = 0; k < 10; k++) {
        float sn = 0.f;
        #pragma unroll
        for (int o = 0; o < 16; o++) { float t = vb[k * 16 + o]; sn += t * t; }
        if (sn > bestn) { bestn = sn; bi = k; }
    }
    best[b] = bi;
    for (int i = 0; i < 160; i++) out_obj[b * 160 + i] = vb[i];
    #pragma unroll
    for (int k = 0; k < 10; k++) out_mask[b * 10 + k] = (k == bi) ? 1.f : 0.f;
}

// ---------------- Decoder ----------------
__global__ void dec1_kernel(const float* __restrict__ v, const int* __restrict__ best,
                            const float* __restrict__ w1, const float* __restrict__ b1,
                            float* __restrict__ h1) {
    int b = blockIdx.x;
    int j = threadIdx.x;
    __shared__ float vs[16];
    int bi = best[b];
    if (threadIdx.x < 16) vs[threadIdx.x] = v[b * 160 + bi * 16 + threadIdx.x];
    __syncthreads();
    float acc = b1[j];
    #pragma unroll
    for (int o = 0; o < 16; o++) acc += vs[o] * w1[(bi * 16 + o) * 512 + j];
    h1[b * 512 + j] = fmaxf(acc, 0.f);
}

template<int ACT>
__global__ void gemm_act_kernel(const float* __restrict__ A, const float* __restrict__ W,
                                const float* __restrict__ bias, float* __restrict__ C,
                                int M, int N, int K) {
    __shared__ float As[16][64];
    __shared__ float Bs[16][64];
    int tid = threadIdx.x;
    int m0 = blockIdx.y * 64, n0 = blockIdx.x * 64;
    int ty = tid >> 4, tx = tid & 15;
    float acc[4][4];
    #pragma unroll
    for (int i = 0; i < 4; i++)
        #pragma unroll
        for (int j = 0; j < 4; j++) acc[i][j] = 0.f;

    int lam = tid >> 2;
    int lak = (tid & 3) * 4;
    int lbk = tid >> 4;
    int lbn = (tid & 15) * 4;

    for (int k0 = 0; k0 < K; k0 += 16) {
        float4 av = *reinterpret_cast<const float4*>(A + (size_t)(m0 + lam) * K + k0 + lak);
        As[lak + 0][lam] = av.x; As[lak + 1][lam] = av.y;
        As[lak + 2][lam] = av.z; As[lak + 3][lam] = av.w;
        #pragma unroll
        for (int i = 0; i < 4; i++) {
            int n = n0 + lbn + i;
            Bs[lbk][lbn + i] = (n < N) ? W[(size_t)(k0 + lbk) * N + n] : 0.f;
        }
        __syncthreads();
        #pragma unroll
        for (int kk = 0; kk < 16; kk++) {
            float af[4], bf[4];
            #pragma unroll
            for (int i = 0; i < 4; i++) af[i] = As[kk][ty * 4 + i];
            #pragma unroll
            for (int j = 0; j < 4; j++) bf[j] = Bs[kk][tx * 4 + j];
            #pragma unroll
            for (int i = 0; i < 4; i++)
                #pragma unroll
                for (int j = 0; j < 4; j++)
                    acc[i][j] += af[i] * bf[j];
        }
        __syncthreads();
    }
    #pragma unroll
    for (int i = 0; i < 4; i++) {
        int m = m0 + ty * 4 + i;
        #pragma unroll
        for (int j = 0; j < 4; j++) {
            int n = n0 + tx * 4 + j;
            if (n < N) {
                float x = acc[i][j] + bias[n];
                if (ACT == 0) x = fmaxf(x, 0.f);
                else          x = 1.f / (1.f + expf(-x));
                C[(size_t)m * N + n] = x;
            }
        }
    }
}

// ---------------- Host launcher ----------------
extern "C" void kernel_launch(void* const* d_in, const int* in_sizes, int n_in,
                              void* d_out, int out_size) {
    const float* image  = (const float*)d_in[0];
    const float* conv_w = (const float*)d_in[1];
    const float* conv_b = (const float*)d_in[2];
    const float* pc_w   = (const float*)d_in[3];
    const float* pc_b   = (const float*)d_in[4];
    const float* W_obj  = (const float*)d_in[5];
    const float* dec_w1 = (const float*)d_in[6];
    const float* dec_b1 = (const float*)d_in[7];
    const float* dec_w2 = (const float*)d_in[8];
    const float* dec_b2 = (const float*)d_in[9];
    const float* dec_w3 = (const float*)d_in[10];
    const float* dec_b3 = (const float*)d_in[11];

    float* out = (float*)d_out;
    float* out_obj  = out;
    float* out_rec  = out + BATCH * 160;
    float* out_mask = out + BATCH * (160 + 784);

    uint32_t* x1p  = nullptr; cudaGetSymbolAddress((void**)&x1p,  g_x1p);
    uint32_t* bpp  = nullptr; cudaGetSymbolAddress((void**)&bpp,  g_bp);
    int*      koff = nullptr; cudaGetSymbolAddress((void**)&koff, g_kofft);
    float* c2   = nullptr; cudaGetSymbolAddress((void**)&c2,   g_c2);
    float* u    = nullptr; cudaGetSymbolAddress((void**)&u,    g_u);
    float* uhat = nullptr; cudaGetSymbolAddress((void**)&uhat, g_uhat);
    float* bij  = nullptr; cudaGetSymbolAddress((void**)&bij,  g_bij);
    float* cij  = nullptr; cudaGetSymbolAddress((void**)&cij,  g_cij);
    float* v    = nullptr; cudaGetSymbolAddress((void**)&v,    g_v);
    int*   best = nullptr; cudaGetSymbolAddress((void**)&best, g_best);
    float* h1   = nullptr; cudaGetSymbolAddress((void**)&h1,   g_h1);
    float* h2   = nullptr; cudaGetSymbolAddress((void**)&h2,   g_h2);

    // 0) pre-split B + offset table
    bsplit_kernel<<<(N2 * K2 + 1023) / 1024, 1024>>>(pc_w, bpp);
    kofft_kernel<<<(K2 + 255) / 256, 256>>>(koff);
    // 1) conv1 + relu -> packed bf16 split
    conv1_kernel<<<dim3(BATCH, 8), 256>>>(image, conv_w, conv_b, x1p);
    // 2) conv2 as split-bf16 tensor-core implicit GEMM
    conv2_mma_kernel<<<dim3(N2 / 128, M2 / 128), 256>>>(x1p, bpp, koff, pc_b, c2);
    // 3) squash -> u
    squash_u_kernel<<<(BATCH * ROUTES + 255) / 256, 256>>>(c2, u);
    // 4) u_hat
    uhat_kernel<<<dim3(ROUTES, BATCH / 32), 256>>>(W_obj, u, uhat);
    // 5) routing (3 iterations)
    zero_bij_kernel<<<(ROUTES * NCAPS + 255) / 256, 256>>>(bij);
    for (int it = 0; it < 3; it++) {
        softmax_routes_kernel<<<NCAPS, 256>>>(bij, cij);
        sv_kernel<<<dim3(BATCH, NCAPS), 128>>>(cij, uhat, v);
        if (it < 2)
            agree_kernel<<<dim3(ROUTES, NCAPS), 256>>>(uhat, v, bij);
    }
    // 6) mask + obj output
    mask_kernel<<<2, 256>>>(v, out_obj, out_mask, best);
    // 7) decoder
    dec1_kernel<<<BATCH, 512>>>(v, best, dec_w1, dec_b1, h1);
    gemm_act_kernel<0><<<dim3(1024 / 64, BATCH / 64), 256>>>(h1, dec_w2, dec_b2, h2, BATCH, 1024, 512);
    gemm_act_kernel<1><<<dim3((784 + 63) / 64, BATCH / 64), 256>>>(h2, dec_w3, dec_b3, out_rec, BATCH, 784, 1024);
}

// round 8
// speedup vs baseline: 1.0286x; 1.0286x over previous
#include <cuda_runtime.h>
#include <cuda_bf16.h>
#include <stdint.h>
#include <math.h>

// ---------------- Problem constants ----------------
#define BATCH 512
#define C1 256
#define ROUTES 1152
#define NCAPS 10
#define CAPDIM 16
#define M2 (BATCH*36)     // 18432
#define K2 20736          // 256*81
#define N2 256
#define FLAT 9216

// ---------------- Device scratch ----------------
__device__ __align__(16) uint32_t g_x1p[BATCH*C1*20*20];     // packed bf16 hi|lo
__device__ __align__(16) uint32_t g_bp[(size_t)N2*K2];       // packed pc_w
__device__ __align__(16) int      g_kofft[K2];
__device__ __align__(16) float g_c2[BATCH*FLAT];
__device__ __align__(16) float g_u[BATCH*FLAT];
__device__ __align__(16) float g_uhat[(size_t)BATCH*ROUTES*NCAPS*CAPDIM];
__device__ __align__(16) float g_bij[ROUTES*NCAPS];
__device__ __align__(16) float g_cij[ROUTES*NCAPS];
__device__ __align__(16) float g_v[BATCH*NCAPS*CAPDIM];
__device__ int   g_best[BATCH];
__device__ __align__(16) float g_h1[BATCH*512];
__device__ __align__(16) float g_h2[BATCH*1024];

// ---------------- pack helper ----------------
__device__ __forceinline__ uint32_t pack_split(float x) {
    __nv_bfloat16 h = __float2bfloat16(x);
    __nv_bfloat16 l = __float2bfloat16(x - __bfloat162float(h));
    return (uint32_t)__bfloat16_as_ushort(h) | ((uint32_t)__bfloat16_as_ushort(l) << 16);
}

__global__ void bsplit_kernel(const float* __restrict__ w, uint32_t* __restrict__ bp) {
    int i = blockIdx.x * 1024 + threadIdx.x;
    if (i < N2 * K2) bp[i] = pack_split(w[i]);
}

__global__ void kofft_kernel(int* __restrict__ tab) {
    int k = blockIdx.x * 256 + threadIdx.x;
    if (k >= K2) return;
    int ci = k / 81, rem = k - ci * 81;
    int ky = rem / 9, kx = rem - ky * 9;
    tab[k] = ci * 400 + ky * 20 + kx;
}

// ---------------- Conv1 ----------------
__global__ void conv1_kernel(const float* __restrict__ img, const float* __restrict__ w,
                             const float* __restrict__ bias, uint32_t* __restrict__ x1p) {
    __shared__ float ism[784];
    __shared__ float wsm[32 * 81];
    int b = blockIdx.x, g = blockIdx.y;
    for (int i = threadIdx.x; i < 784; i += 256) ism[i] = img[b * 784 + i];
    for (int i = threadIdx.x; i < 2592; i += 256) wsm[i] = w[g * 2592 + i];
    __syncthreads();
    for (int idx = threadIdx.x; idx < 32 * 400; idx += 256) {
        int cl = idx / 400, pix = idx - cl * 400;
        int y = pix / 20, x = pix - y * 20;
        const float* wp = &wsm[cl * 81];
        float acc = bias[g * 32 + cl];
        #pragma unroll
        for (int ky = 0; ky < 9; ky++) {
            const float* irow = &ism[(y + ky) * 28 + x];
            #pragma unroll
            for (int kx = 0; kx < 9; kx++)
                acc += irow[kx] * wp[ky * 9 + kx];
        }
        x1p[(size_t)b * 102400 + (size_t)(g * 32 + cl) * 400 + pix] = pack_split(fmaxf(acc, 0.f));
    }
}

// ---------------- Conv2: split-bf16 MMA, 512 threads, 16 warps of 32x32 ----------------
#define BK 16
#define LDS_PAD 24

__device__ __forceinline__ void mma_bf16(float& c0, float& c1, float& c2, float& c3,
                                         uint32_t a0, uint32_t a1, uint32_t a2, uint32_t a3,
                                         uint32_t b0, uint32_t b1) {
    asm volatile(
        "mma.sync.aligned.m16n8k16.row.col.f32.bf16.bf16.f32 "
        "{%0,%1,%2,%3}, {%4,%5,%6,%7}, {%8,%9}, {%0,%1,%2,%3};\n"
        : "+f"(c0), "+f"(c1), "+f"(c2), "+f"(c3)
        : "r"(a0), "r"(a1), "r"(a2), "r"(a3), "r"(b0), "r"(b1));
}

__global__ __launch_bounds__(512, 1)
void conv2_mma_kernel(const uint32_t* __restrict__ x1p, const uint32_t* __restrict__ bp,
                      const int* __restrict__ kofft,
                      const float* __restrict__ bias, float* __restrict__ out) {
    __shared__ __align__(16) __nv_bfloat16 AsH[2][128 * LDS_PAD];
    __shared__ __align__(16) __nv_bfloat16 AsL[2][128 * LDS_PAD];
    __shared__ __align__(16) __nv_bfloat16 BsH[2][128 * LDS_PAD];
    __shared__ __align__(16) __nv_bfloat16 BsL[2][128 * LDS_PAD];

    const int t = threadIdx.x;
    const int m0 = blockIdx.y * 128;
    const int n0 = blockIdx.x * 128;

    // loader mapping: row = t>>2 (0..127), k-quarter = (t&3)*4
    const int lr  = t >> 2;
    const int lkh = (t & 3) * 4;

    const int mg = m0 + lr;
    const int bb = mg / 36;
    const int ss = mg - bb * 36;
    const int oy = ss / 6, ox = ss - oy * 6;
    const uint32_t* abase = x1p + (size_t)bb * 102400 + oy * 40 + ox * 2;
    const uint32_t* bbase = bp + (size_t)(n0 + lr) * K2;
    const int sa = lr * LDS_PAD + lkh;   // bf16 elems; byte = lr*48 + lkh*2 (8B aligned)

    // compute mapping: 16 warps = 4m x 4n, warp tile 32x32
    const int wid = t >> 5;
    const int wm = wid >> 2;          // 0..3
    const int wn = wid & 3;           // 0..3
    const int lane = t & 31;
    const int qr = lane >> 2;         // 0..7
    const int qc = (lane & 3) * 2;    // 0,2,4,6

    float acc[2][4][4];
    #pragma unroll
    for (int i = 0; i < 2; i++)
        #pragma unroll
        for (int j = 0; j < 4; j++)
            #pragma unroll
            for (int r = 0; r < 4; r++) acc[i][j][r] = 0.f;

    uint32_t av[4], bv4x, bv4y, bv4z, bv4w;

    // prologue: load k-step 0
    {
        int4 o = *reinterpret_cast<const int4*>(kofft + lkh);
        av[0] = abase[o.x]; av[1] = abase[o.y]; av[2] = abase[o.z]; av[3] = abase[o.w];
        uint4 u = *reinterpret_cast<const uint4*>(bbase + lkh);
        bv4x = u.x; bv4y = u.y; bv4z = u.z; bv4w = u.w;
        uint2 ah2, al2, bh2, bl2;
        ah2.x = __byte_perm(av[0], av[1], 0x5410); ah2.y = __byte_perm(av[2], av[3], 0x5410);
        al2.x = __byte_perm(av[0], av[1], 0x7632); al2.y = __byte_perm(av[2], av[3], 0x7632);
        bh2.x = __byte_perm(bv4x, bv4y, 0x5410);   bh2.y = __byte_perm(bv4z, bv4w, 0x5410);
        bl2.x = __byte_perm(bv4x, bv4y, 0x7632);   bl2.y = __byte_perm(bv4z, bv4w, 0x7632);
        *reinterpret_cast<uint2*>(&AsH[0][sa]) = ah2;
        *reinterpret_cast<uint2*>(&AsL[0][sa]) = al2;
        *reinterpret_cast<uint2*>(&BsH[0][sa]) = bh2;
        *reinterpret_cast<uint2*>(&BsL[0][sa]) = bl2;
    }
    __syncthreads();

    const int NSTEP = K2 / BK;   // 1296
    for (int s = 0; s < NSTEP; s++) {
        const int cur = s & 1;
        const bool more = (s + 1 < NSTEP);
        if (more) {
            int kk = (s + 1) * BK + lkh;
            int4 o = *reinterpret_cast<const int4*>(kofft + kk);
            av[0] = abase[o.x]; av[1] = abase[o.y]; av[2] = abase[o.z]; av[3] = abase[o.w];
            uint4 u = *reinterpret_cast<const uint4*>(bbase + kk);
            bv4x = u.x; bv4y = u.y; bv4z = u.z; bv4w = u.w;
        }

        // compute on stage `cur`: warp tile 32x32, 2 m-frags x 4 n-frags x 3 terms
        {
            uint32_t ah[2][4], al[2][4], bh[4][2], bl[4][2];
            #pragma unroll
            for (int i = 0; i < 2; i++) {
                int r0 = (wm * 32 + i * 16 + qr) * LDS_PAD;
                int r8 = r0 + 8 * LDS_PAD;
                ah[i][0] = *reinterpret_cast<const uint32_t*>(&AsH[cur][r0 + qc]);
                ah[i][1] = *reinterpret_cast<const uint32_t*>(&AsH[cur][r8 + qc]);
                ah[i][2] = *reinterpret_cast<const uint32_t*>(&AsH[cur][r0 + qc + 8]);
                ah[i][3] = *reinterpret_cast<const uint32_t*>(&AsH[cur][r8 + qc + 8]);
                al[i][0] = *reinterpret_cast<const uint32_t*>(&AsL[cur][r0 + qc]);
                al[i][1] = *reinterpret_cast<const uint32_t*>(&AsL[cur][r8 + qc]);
                al[i][2] = *reinterpret_cast<const uint32_t*>(&AsL[cur][r0 + qc + 8]);
                al[i][3] = *reinterpret_cast<const uint32_t*>(&AsL[cur][r8 + qc + 8]);
            }
            #pragma unroll
            for (int j = 0; j < 4; j++) {
                int nr = (wn * 32 + j * 8 + qr) * LDS_PAD;
                bh[j][0] = *reinterpret_cast<const uint32_t*>(&BsH[cur][nr + qc]);
                bh[j][1] = *reinterpret_cast<const uint32_t*>(&BsH[cur][nr + qc + 8]);
                bl[j][0] = *reinterpret_cast<const uint32_t*>(&BsL[cur][nr + qc]);
                bl[j][1] = *reinterpret_cast<const uint32_t*>(&BsL[cur][nr + qc + 8]);
            }
            #pragma unroll
            for (int i = 0; i < 2; i++)
                #pragma unroll
                for (int j = 0; j < 4; j++) {
                    mma_bf16(acc[i][j][0], acc[i][j][1], acc[i][j][2], acc[i][j][3],
                             ah[i][0], ah[i][1], ah[i][2], ah[i][3], bh[j][0], bh[j][1]);
                    mma_bf16(acc[i][j][0], acc[i][j][1], acc[i][j][2], acc[i][j][3],
                             ah[i][0], ah[i][1], ah[i][2], ah[i][3], bl[j][0], bl[j][1]);
                    mma_bf16(acc[i][j][0], acc[i][j][1], acc[i][j][2], acc[i][j][3],
                             al[i][0], al[i][1], al[i][2], al[i][3], bh[j][0], bh[j][1]);
                }
        }

        if (more) {
            int nxt = cur ^ 1;
            uint2 ah2, al2, bh2, bl2;
            ah2.x = __byte_perm(av[0], av[1], 0x5410); ah2.y = __byte_perm(av[2], av[3], 0x5410);
            al2.x = __byte_perm(av[0], av[1], 0x7632); al2.y = __byte_perm(av[2], av[3], 0x7632);
            bh2.x = __byte_perm(bv4x, bv4y, 0x5410);   bh2.y = __byte_perm(bv4z, bv4w, 0x5410);
            bl2.x = __byte_perm(bv4x, bv4y, 0x7632);   bl2.y = __byte_perm(bv4z, bv4w, 0x7632);
            *reinterpret_cast<uint2*>(&AsH[nxt][sa]) = ah2;
            *reinterpret_cast<uint2*>(&AsL[nxt][sa]) = al2;
            *reinterpret_cast<uint2*>(&BsH[nxt][sa]) = bh2;
            *reinterpret_cast<uint2*>(&BsL[nxt][sa]) = bl2;
        }
        __syncthreads();
    }

    // epilogue
    #pragma unroll
    for (int i = 0; i < 2; i++) {
        #pragma unroll
        for (int j = 0; j < 4; j++) {
            int r = m0 + wm * 32 + i * 16 + qr;
            int c = n0 + wn * 32 + j * 8 + qc;
            #pragma unroll
            for (int rr = 0; rr < 2; rr++) {
                int m = r + rr * 8;
                int b = m / 36, sidx = m - b * 36;
                float* op = out + (size_t)b * FLAT + sidx;
                op[(c + 0) * 36] = acc[i][j][rr * 2 + 0] + bias[c + 0];
                op[(c + 1) * 36] = acc[i][j][rr * 2 + 1] + bias[c + 1];
            }
        }
    }
}

// ---------------- Squash u ----------------
__global__ void squash_u_kernel(const float* __restrict__ c2, float* __restrict__ u) {
    int i = blockIdx.x * 256 + threadIdx.x;
    if (i >= BATCH * ROUTES) return;
    const float4* p = reinterpret_cast<const float4*>(c2 + (size_t)i * 8);
    float4 a = p[0], b = p[1];
    float sn = a.x*a.x + a.y*a.y + a.z*a.z + a.w*a.w
             + b.x*b.x + b.y*b.y + b.z*b.z + b.w*b.w + 1e-7f;
    float sc = sqrtf(sn) / (1.f + sn);
    float4 oa = make_float4(a.x*sc, a.y*sc, a.z*sc, a.w*sc);
    float4 ob = make_float4(b.x*sc, b.y*sc, b.z*sc, b.w*sc);
    float4* q = reinterpret_cast<float4*>(u + (size_t)i * 8);
    q[0] = oa; q[1] = ob;
}

// ---------------- u_hat ----------------
__global__ void uhat_kernel(const float* __restrict__ W, const float* __restrict__ u,
                            float* __restrict__ uhat) {
    __shared__ float Wsm[1280];
    __shared__ float usm[256];
    int r = blockIdx.x;
    int bg = blockIdx.y;
    for (int i = threadIdx.x; i < 1280; i += 256) Wsm[i] = W[(size_t)r * 1280 + i];
    {
        int i = threadIdx.x;
        int bb = bg * 32 + (i >> 3);
        usm[i] = u[(size_t)bb * FLAT + r * 8 + (i & 7)];
    }
    __syncthreads();
    for (int i = threadIdx.x; i < 5120; i += 256) {
        int bi = i / 160, ko = i - bi * 160;
        const float* wp = &Wsm[ko * 8];
        const float* up = &usm[bi * 8];
        float acc = 0.f;
        #pragma unroll
        for (int c = 0; c < 8; c++) acc += wp[c] * up[c];
        uhat[((size_t)(bg * 32 + bi) * ROUTES + r) * 160 + ko] = acc;
    }
}

// ---------------- Routing ----------------
__global__ void zero_bij_kernel(float* __restrict__ bij) {
    int i = blockIdx.x * 256 + threadIdx.x;
    if (i < ROUTES * NCAPS) bij[i] = 0.f;
}

__global__ void softmax_routes_kernel(const float* __restrict__ b, float* __restrict__ c) {
    int k = blockIdx.x;
    __shared__ float red[256];
    int tid = threadIdx.x;
    float m = -1e30f;
    for (int r = tid; r < ROUTES; r += 256) m = fmaxf(m, b[r * 10 + k]);
    red[tid] = m; __syncthreads();
    for (int s = 128; s > 0; s >>= 1) {
        if (tid < s) red[tid] = fmaxf(red[tid], red[tid + s]);
        __syncthreads();
    }
    m = red[0]; __syncthreads();
    float sum = 0.f;
    for (int r = tid; r < ROUTES; r += 256) sum += expf(b[r * 10 + k] - m);
    red[tid] = sum; __syncthreads();
    for (int s = 128; s > 0; s >>= 1) {
        if (tid < s) red[tid] += red[tid + s];
        __syncthreads();
    }
    float inv = 1.f / red[0];
    for (int r = tid; r < ROUTES; r += 256) c[r * 10 + k] = expf(b[r * 10 + k] - m) * inv;
}

__global__ void sv_kernel(const float* __restrict__ cij, const float* __restrict__ uhat,
                          float* __restrict__ v) {
    int b = blockIdx.x, k = blockIdx.y;
    int tid = threadIdx.x;
    float acc[16];
    #pragma unroll
    for (int o = 0; o < 16; o++) acc[o] = 0.f;
    for (int r = tid; r < ROUTES; r += 128) {
        float cc = cij[r * 10 + k];
        const float4* p = reinterpret_cast<const float4*>(uhat + ((size_t)(b * ROUTES + r) * 10 + k) * 16);
        float4 x0 = p[0], x1 = p[1], x2 = p[2], x3 = p[3];
        acc[0]  += cc * x0.x; acc[1]  += cc * x0.y; acc[2]  += cc * x0.z; acc[3]  += cc * x0.w;
        acc[4]  += cc * x1.x; acc[5]  += cc * x1.y; acc[6]  += cc * x1.z; acc[7]  += cc * x1.w;
        acc[8]  += cc * x2.x; acc[9]  += cc * x2.y; acc[10] += cc * x2.z; acc[11] += cc * x2.w;
        acc[12] += cc * x3.x; acc[13] += cc * x3.y; acc[14] += cc * x3.z; acc[15] += cc * x3.w;
    }
    __shared__ float red[128 * 16];
    #pragma unroll
    for (int o = 0; o < 16; o++) red[tid * 16 + o] = acc[o];
    __syncthreads();
    for (int s = 64; s > 0; s >>= 1) {
        if (tid < s) {
            #pragma unroll
            for (int o = 0; o < 16; o++) red[tid * 16 + o] += red[(tid + s) * 16 + o];
        }
        __syncthreads();
    }
    if (tid == 0) {
        float sn = 0.f;
        #pragma unroll
        for (int o = 0; o < 16; o++) sn += red[o] * red[o];
        float sc = sqrtf(sn) / (1.f + sn);
        #pragma unroll
        for (int o = 0; o < 16; o++) v[(b * 10 + k) * 16 + o] = red[o] * sc;
    }
}

__global__ void agree_kernel(const float* __restrict__ uhat, const float* __restrict__ v,
                             float* __restrict__ bij) {
    int r = blockIdx.x, k = blockIdx.y;
    int tid = threadIdx.x;
    __shared__ __align__(16) float vsm[BATCH * 16];
    __shared__ float red[256];
    for (int i = tid; i < BATCH * 16; i += 256) {
        int bb = i >> 4, o = i & 15;
        vsm[i] = v[(bb * 10 + k) * 16 + o];
    }
    __syncthreads();
    float acc = 0.f;
    for (int bb = tid; bb < BATCH; bb += 256) {
        const float4* p = reinterpret_cast<const float4*>(uhat + ((size_t)(bb * ROUTES + r) * 10 + k) * 16);
        const float4* q = reinterpret_cast<const float4*>(&vsm[bb * 16]);
        float4 a0 = p[0], a1 = p[1], a2 = p[2], a3 = p[3];
        float4 b0 = q[0], b1 = q[1], b2 = q[2], b3 = q[3];
        acc += a0.x*b0.x + a0.y*b0.y + a0.z*b0.z + a0.w*b0.w;
        acc += a1.x*b1.x + a1.y*b1.y + a1.z*b1.z + a1.w*b1.w;
        acc += a2.x*b2.x + a2.y*b2.y + a2.z*b2.z + a2.w*b2.w;
        acc += a3.x*b3.x + a3.y*b3.y + a3.z*b3.z + a3.w*b3.w;
    }
    red[tid] = acc; __syncthreads();
    for (int s = 128; s > 0; s >>= 1) {
        if (tid < s) red[tid] += red[tid + s];
        __syncthreads();
    }
    if (tid == 0) bij[r * 10 + k] += red[0] * (1.f / (float)BATCH);
}

// ---------------- Mask / argmax ----------------
__global__ void mask_kernel(const float* __restrict__ v, float* __restrict__ out_obj,
                            float* __restrict__ out_mask, int* __restrict__ best) {
    int b = blockIdx.x * blockDim.x + threadIdx.x;
    if (b >= BATCH) return;
    const float* vb = v + b * 160;
    float bestn = -1.f; int bi = 0;
    #pragma unroll
    for (int k = 0; k < 10; k++) {
        float sn = 0.f;
        #pragma unroll
        for (int o = 0; o < 16; o++) { float t = vb[k * 16 + o]; sn += t * t; }
        if (sn > bestn) { bestn = sn; bi = k; }
    }
    best[b] = bi;
    for (int i = 0; i < 160; i++) out_obj[b * 160 + i] = vb[i];
    #pragma unroll
    for (int k = 0; k < 10; k++) out_mask[b * 10 + k] = (k == bi) ? 1.f : 0.f;
}

// ---------------- Decoder ----------------
__global__ void dec1_kernel(const float* __restrict__ v, const int* __restrict__ best,
                            const float* __restrict__ w1, const float* __restrict__ b1,
                            float* __restrict__ h1) {
    int b = blockIdx.x;
    int j = threadIdx.x;
    __shared__ float vs[16];
    int bi = best[b];
    if (threadIdx.x < 16) vs[threadIdx.x] = v[b * 160 + bi * 16 + threadIdx.x];
    __syncthreads();
    float acc = b1[j];
    #pragma unroll
    for (int o = 0; o < 16; o++) acc += vs[o] * w1[(bi * 16 + o) * 512 + j];
    h1[b * 512 + j] = fmaxf(acc, 0.f);
}

template<int ACT>
__global__ void gemm_act_kernel(const float* __restrict__ A, const float* __restrict__ W,
                                const float* __restrict__ bias, float* __restrict__ C,
                                int M, int N, int K) {
    __shared__ float As[16][64];
    __shared__ float Bs[16][64];
    int tid = threadIdx.x;
    int m0 = blockIdx.y * 64, n0 = blockIdx.x * 64;
    int ty = tid >> 4, tx = tid & 15;
    float acc[4][4];
    #pragma unroll
    for (int i = 0; i < 4; i++)
        #pragma unroll
        for (int j = 0; j < 4; j++) acc[i][j] = 0.f;

    int lam = tid >> 2;
    int lak = (tid & 3) * 4;
    int lbk = tid >> 4;
    int lbn = (tid & 15) * 4;

    for (int k0 = 0; k0 < K; k0 += 16) {
        float4 av = *reinterpret_cast<const float4*>(A + (size_t)(m0 + lam) * K + k0 + lak);
        As[lak + 0][lam] = av.x; As[lak + 1][lam] = av.y;
        As[lak + 2][lam] = av.z; As[lak + 3][lam] = av.w;
        #pragma unroll
        for (int i = 0; i < 4; i++) {
            int n = n0 + lbn + i;
            Bs[lbk][lbn + i] = (n < N) ? W[(size_t)(k0 + lbk) * N + n] : 0.f;
        }
        __syncthreads();
        #pragma unroll
        for (int kk = 0; kk < 16; kk++) {
            float af[4], bf[4];
            #pragma unroll
            for (int i = 0; i < 4; i++) af[i] = As[kk][ty * 4 + i];
            #pragma unroll
            for (int j = 0; j < 4; j++) bf[j] = Bs[kk][tx * 4 + j];
            #pragma unroll
            for (int i = 0; i < 4; i++)
                #pragma unroll
                for (int j = 0; j < 4; j++)
                    acc[i][j] += af[i] * bf[j];
        }
        __syncthreads();
    }
    #pragma unroll
    for (int i = 0; i < 4; i++) {
        int m = m0 + ty * 4 + i;
        #pragma unroll
        for (int j = 0; j < 4; j++) {
            int n = n0 + tx * 4 + j;
            if (n < N) {
                float x = acc[i][j] + bias[n];
                if (ACT == 0) x = fmaxf(x, 0.f);
                else          x = 1.f / (1.f + expf(-x));
                C[(size_t)m * N + n] = x;
            }
        }
    }
}

// ---------------- Host launcher ----------------
extern "C" void kernel_launch(void* const* d_in, const int* in_sizes, int n_in,
                              void* d_out, int out_size) {
    const float* image  = (const float*)d_in[0];
    const float* conv_w = (const float*)d_in[1];
    const float* conv_b = (const float*)d_in[2];
    const float* pc_w   = (const float*)d_in[3];
    const float* pc_b   = (const float*)d_in[4];
    const float* W_obj  = (const float*)d_in[5];
    const float* dec_w1 = (const float*)d_in[6];
    const float* dec_b1 = (const float*)d_in[7];
    const float* dec_w2 = (const float*)d_in[8];
    const float* dec_b2 = (const float*)d_in[9];
    const float* dec_w3 = (const float*)d_in[10];
    const float* dec_b3 = (const float*)d_in[11];

    float* out = (float*)d_out;
    float* out_obj  = out;
    float* out_rec  = out + BATCH * 160;
    float* out_mask = out + BATCH * (160 + 784);

    uint32_t* x1p  = nullptr; cudaGetSymbolAddress((void**)&x1p,  g_x1p);
    uint32_t* bpp  = nullptr; cudaGetSymbolAddress((void**)&bpp,  g_bp);
    int*      koff = nullptr; cudaGetSymbolAddress((void**)&koff, g_kofft);
    float* c2   = nullptr; cudaGetSymbolAddress((void**)&c2,   g_c2);
    float* u    = nullptr; cudaGetSymbolAddress((void**)&u,    g_u);
    float* uhat = nullptr; cudaGetSymbolAddress((void**)&uhat, g_uhat);
    float* bij  = nullptr; cudaGetSymbolAddress((void**)&bij,  g_bij);
    float* cij  = nullptr; cudaGetSymbolAddress((void**)&cij,  g_cij);
    float* v    = nullptr; cudaGetSymbolAddress((void**)&v,    g_v);
    int*   best = nullptr; cudaGetSymbolAddress((void**)&best, g_best);
    float* h1   = nullptr; cudaGetSymbolAddress((void**)&h1,   g_h1);
    float* h2   = nullptr; cudaGetSymbolAddress((void**)&h2,   g_h2);

    // 0) pre-split B + offset table
    bsplit_kernel<<<(N2 * K2 + 1023) / 1024, 1024>>>(pc_w, bpp);
    kofft_kernel<<<(K2 + 255) / 256, 256>>>(koff);
    // 1) conv1 + relu -> packed bf16 split
    conv1_kernel<<<dim3(BATCH, 8), 256>>>(image, conv_w, conv_b, x1p);
    // 2) conv2 split-bf16 MMA, 512 threads
    conv2_mma_kernel<<<dim3(N2 / 128, M2 / 128), 512>>>(x1p, bpp, koff, pc_b, c2);
    // 3) squash -> u
    squash_u_kernel<<<(BATCH * ROUTES + 255) / 256, 256>>>(c2, u);
    // 4) u_hat
    uhat_kernel<<<dim3(ROUTES, BATCH / 32), 256>>>(W_obj, u, uhat);
    // 5) routing (3 iterations)
    zero_bij_kernel<<<(ROUTES * NCAPS + 255) / 256, 256>>>(bij);
    for (int it = 0; it < 3; it++) {
        softmax_routes_kernel<<<NCAPS, 256>>>(bij, cij);
        sv_kernel<<<dim3(BATCH, NCAPS), 128>>>(cij, uhat, v);
        if (it < 2)
            agree_kernel<<<dim3(ROUTES, NCAPS), 256>>>(uhat, v, bij);
    }
    // 6) mask + obj output
    mask_kernel<<<2, 256>>>(v, out_obj, out_mask, best);
    // 7) decoder
    dec1_kernel<<<BATCH, 512>>>(v, best, dec_w1, dec_b1, h1);
    gemm_act_kernel<0><<<dim3(1024 / 64, BATCH / 64), 256>>>(h1, dec_w2, dec_b2, h2, BATCH, 1024, 512);
    gemm_act_kernel<1><<<dim3((784 + 63) / 64, BATCH / 64), 256>>>(h2, dec_w3, dec_b3, out_rec, BATCH, 784, 1024);
}

// round 12
// speedup vs baseline: 1.1542x; 1.1221x over previous
#include <cuda_runtime.h>
#include <cuda_bf16.h>
#include <stdint.h>
#include <math.h>

// ---------------- Problem constants ----------------
#define BATCH 512
#define C1 256
#define ROUTES 1152
#define NCAPS 10
#define CAPDIM 16
#define M2 (BATCH*36)     // 18432
#define K2 20736          // 256*81
#define N2 256
#define FLAT 9216

// ---------------- Device scratch ----------------
// Big buffer shared by aim (im2col, live until conv2) and uhat (live after conv2).
// aim bytes = M2*K2*4 = 1,528,823,808 ; uhat bytes = 512*10*1152*16*4 = 377,487,360.
#define BIG_BYTES ((size_t)M2 * K2 * 4)
__device__ __align__(128) unsigned char g_big[BIG_BYTES];
__device__ __align__(16) uint32_t g_x1p[BATCH*C1*20*20];          // packed bf16 hi|lo (210MB)
__device__ __align__(16) uint32_t g_bp[(size_t)N2*K2];            // packed pc_w (84MB)
__device__ __align__(16) int      g_kofft[K2];
__device__ __align__(16) float g_c2[BATCH*FLAT];
__device__ __align__(16) float g_u[BATCH*FLAT];
__device__ __align__(16) float g_bij[ROUTES*NCAPS];
__device__ __align__(16) float g_cij[ROUTES*NCAPS];
__device__ __align__(16) float g_v[BATCH*NCAPS*CAPDIM];
__device__ int   g_best[BATCH];
__device__ __align__(16) float g_h1[BATCH*512];
__device__ __align__(16) float g_h2[BATCH*1024];

// ---------------- pack helper ----------------
__device__ __forceinline__ uint32_t pack_split(float x) {
    __nv_bfloat16 h = __float2bfloat16(x);
    __nv_bfloat16 l = __float2bfloat16(x - __bfloat162float(h));
    return (uint32_t)__bfloat16_as_ushort(h) | ((uint32_t)__bfloat16_as_ushort(l) << 16);
}

__global__ void bsplit_kernel(const float* __restrict__ w, uint32_t* __restrict__ bp) {
    int i = blockIdx.x * 1024 + threadIdx.x;
    if (i < N2 * K2) bp[i] = pack_split(w[i]);
}

__global__ void kofft_kernel(int* __restrict__ tab) {
    int k = blockIdx.x * 256 + threadIdx.x;
    if (k >= K2) return;
    int ci = k / 81, rem = k - ci * 81;
    int ky = rem / 9, kx = rem - ky * 9;
    tab[k] = ci * 400 + ky * 20 + kx;
}

// ---------------- Conv1 -> packed split ----------------
__global__ void conv1_kernel(const float* __restrict__ img, const float* __restrict__ w,
                             const float* __restrict__ bias, uint32_t* __restrict__ x1p) {
    __shared__ float ism[784];
    __shared__ float wsm[32 * 81];
    int b = blockIdx.x, g = blockIdx.y;
    for (int i = threadIdx.x; i < 784; i += 256) ism[i] = img[b * 784 + i];
    for (int i = threadIdx.x; i < 2592; i += 256) wsm[i] = w[g * 2592 + i];
    __syncthreads();
    for (int idx = threadIdx.x; idx < 32 * 400; idx += 256) {
        int cl = idx / 400, pix = idx - cl * 400;
        int y = pix / 20, x = pix - y * 20;
        const float* wp = &wsm[cl * 81];
        float acc = bias[g * 32 + cl];
        #pragma unroll
        for (int ky = 0; ky < 9; ky++) {
            const float* irow = &ism[(y + ky) * 28 + x];
            #pragma unroll
            for (int kx = 0; kx < 9; kx++)
                acc += irow[kx] * wp[ky * 9 + kx];
        }
        x1p[(size_t)b * 102400 + (size_t)(g * 32 + cl) * 400 + pix] = pack_split(fmaxf(acc, 0.f));
    }
}

// ---------------- im2col materialization: A[m][k] packed ----------------
__global__ void im2col_kernel(const uint32_t* __restrict__ x1p, const int* __restrict__ kofft,
                              uint32_t* __restrict__ aim) {
    int m = blockIdx.x;
    int b = m / 36, s = m - b * 36;
    int oy = s / 6, ox = s - oy * 6;
    const uint32_t* base = x1p + (size_t)b * 102400 + oy * 40 + ox * 2;
    uint32_t* dst = aim + (size_t)m * K2;
    for (int k = threadIdx.x; k < K2; k += 256)
        dst[k] = base[kofft[k]];
}

// ---------------- Conv2: split-bf16 MMA, coalesced A from im2col ----------------
#define BK 16
#define LDS_PAD 24

__device__ __forceinline__ void mma_bf16(float& c0, float& c1, float& c2, float& c3,
                                         uint32_t a0, uint32_t a1, uint32_t a2, uint32_t a3,
                                         uint32_t b0, uint32_t b1) {
    asm volatile(
        "mma.sync.aligned.m16n8k16.row.col.f32.bf16.bf16.f32 "
        "{%0,%1,%2,%3}, {%4,%5,%6,%7}, {%8,%9}, {%0,%1,%2,%3};\n"
        : "+f"(c0), "+f"(c1), "+f"(c2), "+f"(c3)
        : "r"(a0), "r"(a1), "r"(a2), "r"(a3), "r"(b0), "r"(b1));
}

__global__ __launch_bounds__(512, 1)
void conv2_mma_kernel(const uint32_t* __restrict__ aim, const uint32_t* __restrict__ bp,
                      const float* __restrict__ bias, float* __restrict__ out) {
    __shared__ __align__(16) __nv_bfloat16 AsH[2][128 * LDS_PAD];
    __shared__ __align__(16) __nv_bfloat16 AsL[2][128 * LDS_PAD];
    __shared__ __align__(16) __nv_bfloat16 BsH[2][128 * LDS_PAD];
    __shared__ __align__(16) __nv_bfloat16 BsL[2][128 * LDS_PAD];

    const int t = threadIdx.x;
    const int m0 = blockIdx.y * 128;
    const int n0 = blockIdx.x * 128;

    // loader: row = t>>2 (0..127), k-quarter = (t&3)*4
    const int lr  = t >> 2;
    const int kq  = (t & 3) * 4;

    const uint32_t* abase = aim + (size_t)(m0 + lr) * K2;
    const uint32_t* bbase = bp + (size_t)(n0 + lr) * K2;
    const int sa = lr * LDS_PAD + kq;

    // compute mapping: 16 warps = 4m x 4n, warp tile 32x32
    const int wid = t >> 5;
    const int wm = wid >> 2;
    const int wn = wid & 3;
    const int lane = t & 31;
    const int qr = lane >> 2;
    const int qc = (lane & 3) * 2;

    float acc[2][4][4];
    #pragma unroll
    for (int i = 0; i < 2; i++)
        #pragma unroll
        for (int j = 0; j < 4; j++)
            #pragma unroll
            for (int r = 0; r < 4; r++) acc[i][j][r] = 0.f;

    uint4 ua, ub;

    // prologue
    {
        ua = *reinterpret_cast<const uint4*>(abase + kq);
        ub = *reinterpret_cast<const uint4*>(bbase + kq);
        uint2 ah2, al2, bh2, bl2;
        ah2.x = __byte_perm(ua.x, ua.y, 0x5410); ah2.y = __byte_perm(ua.z, ua.w, 0x5410);
        al2.x = __byte_perm(ua.x, ua.y, 0x7632); al2.y = __byte_perm(ua.z, ua.w, 0x7632);
        bh2.x = __byte_perm(ub.x, ub.y, 0x5410); bh2.y = __byte_perm(ub.z, ub.w, 0x5410);
        bl2.x = __byte_perm(ub.x, ub.y, 0x7632); bl2.y = __byte_perm(ub.z, ub.w, 0x7632);
        *reinterpret_cast<uint2*>(&AsH[0][sa]) = ah2;
        *reinterpret_cast<uint2*>(&AsL[0][sa]) = al2;
        *reinterpret_cast<uint2*>(&BsH[0][sa]) = bh2;
        *reinterpret_cast<uint2*>(&BsL[0][sa]) = bl2;
    }
    __syncthreads();

    const int NSTEP = K2 / BK;   // 1296
    for (int s = 0; s < NSTEP; s++) {
        const int cur = s & 1;
        const bool more = (s + 1 < NSTEP);
        if (more) {
            int kk = (s + 1) * BK + kq;
            ua = *reinterpret_cast<const uint4*>(abase + kk);
            ub = *reinterpret_cast<const uint4*>(bbase + kk);
        }

        {
            uint32_t ah[2][4], al[2][4], bh[4][2], bl[4][2];
            #pragma unroll
            for (int i = 0; i < 2; i++) {
                int r0 = (wm * 32 + i * 16 + qr) * LDS_PAD;
                int r8 = r0 + 8 * LDS_PAD;
                ah[i][0] = *reinterpret_cast<const uint32_t*>(&AsH[cur][r0 + qc]);
                ah[i][1] = *reinterpret_cast<const uint32_t*>(&AsH[cur][r8 + qc]);
                ah[i][2] = *reinterpret_cast<const uint32_t*>(&AsH[cur][r0 + qc + 8]);
                ah[i][3] = *reinterpret_cast<const uint32_t*>(&AsH[cur][r8 + qc + 8]);
                al[i][0] = *reinterpret_cast<const uint32_t*>(&AsL[cur][r0 + qc]);
                al[i][1] = *reinterpret_cast<const uint32_t*>(&AsL[cur][r8 + qc]);
                al[i][2] = *reinterpret_cast<const uint32_t*>(&AsL[cur][r0 + qc + 8]);
                al[i][3] = *reinterpret_cast<const uint32_t*>(&AsL[cur][r8 + qc + 8]);
            }
            #pragma unroll
            for (int j = 0; j < 4; j++) {
                int nr = (wn * 32 + j * 8 + qr) * LDS_PAD;
                bh[j][0] = *reinterpret_cast<const uint32_t*>(&BsH[cur][nr + qc]);
                bh[j][1] = *reinterpret_cast<const uint32_t*>(&BsH[cur][nr + qc + 8]);
                bl[j][0] = *reinterpret_cast<const uint32_t*>(&BsL[cur][nr + qc]);
                bl[j][1] = *reinterpret_cast<const uint32_t*>(&BsL[cur][nr + qc + 8]);
            }
            #pragma unroll
            for (int i = 0; i < 2; i++)
                #pragma unroll
                for (int j = 0; j < 4; j++) {
                    mma_bf16(acc[i][j][0], acc[i][j][1], acc[i][j][2], acc[i][j][3],
                             ah[i][0], ah[i][1], ah[i][2], ah[i][3], bh[j][0], bh[j][1]);
                    mma_bf16(acc[i][j][0], acc[i][j][1], acc[i][j][2], acc[i][j][3],
                             ah[i][0], ah[i][1], ah[i][2], ah[i][3], bl[j][0], bl[j][1]);
                    mma_bf16(acc[i][j][0], acc[i][j][1], acc[i][j][2], acc[i][j][3],
                             al[i][0], al[i][1], al[i][2], al[i][3], bh[j][0], bh[j][1]);
                }
        }

        if (more) {
            int nxt = cur ^ 1;
            uint2 ah2, al2, bh2, bl2;
            ah2.x = __byte_perm(ua.x, ua.y, 0x5410); ah2.y = __byte_perm(ua.z, ua.w, 0x5410);
            al2.x = __byte_perm(ua.x, ua.y, 0x7632); al2.y = __byte_perm(ua.z, ua.w, 0x7632);
            bh2.x = __byte_perm(ub.x, ub.y, 0x5410); bh2.y = __byte_perm(ub.z, ub.w, 0x5410);
            bl2.x = __byte_perm(ub.x, ub.y, 0x7632); bl2.y = __byte_perm(ub.z, ub.w, 0x7632);
            *reinterpret_cast<uint2*>(&AsH[nxt][sa]) = ah2;
            *reinterpret_cast<uint2*>(&AsL[nxt][sa]) = al2;
            *reinterpret_cast<uint2*>(&BsH[nxt][sa]) = bh2;
            *reinterpret_cast<uint2*>(&BsL[nxt][sa]) = bl2;
        }
        __syncthreads();
    }

    // epilogue
    #pragma unroll
    for (int i = 0; i < 2; i++) {
        #pragma unroll
        for (int j = 0; j < 4; j++) {
            int r = m0 + wm * 32 + i * 16 + qr;
            int c = n0 + wn * 32 + j * 8 + qc;
            #pragma unroll
            for (int rr = 0; rr < 2; rr++) {
                int m = r + rr * 8;
                int b = m / 36, sidx = m - b * 36;
                float* op = out + (size_t)b * FLAT + sidx;
                op[(c + 0) * 36] = acc[i][j][rr * 2 + 0] + bias[c + 0];
                op[(c + 1) * 36] = acc[i][j][rr * 2 + 1] + bias[c + 1];
            }
        }
    }
}

// ---------------- Squash u ----------------
__global__ void squash_u_kernel(const float* __restrict__ c2, float* __restrict__ u) {
    int i = blockIdx.x * 256 + threadIdx.x;
    if (i >= BATCH * ROUTES) return;
    const float4* p = reinterpret_cast<const float4*>(c2 + (size_t)i * 8);
    float4 a = p[0], b = p[1];
    float sn = a.x*a.x + a.y*a.y + a.z*a.z + a.w*a.w
             + b.x*b.x + b.y*b.y + b.z*b.z + b.w*b.w + 1e-7f;
    float sc = sqrtf(sn) / (1.f + sn);
    float4 oa = make_float4(a.x*sc, a.y*sc, a.z*sc, a.w*sc);
    float4 ob = make_float4(b.x*sc, b.y*sc, b.z*sc, b.w*sc);
    float4* q = reinterpret_cast<float4*>(u + (size_t)i * 8);
    q[0] = oa; q[1] = ob;
}

// ---------------- u_hat -> layout [b][k][r][o] ----------------
__global__ void uhat_kernel(const float* __restrict__ W, const float* __restrict__ u,
                            float* __restrict__ uhat) {
    __shared__ float Wsm[1280];
    __shared__ float usm[256];
    int r = blockIdx.x;
    int bg = blockIdx.y;
    for (int i = threadIdx.x; i < 1280; i += 256) Wsm[i] = W[(size_t)r * 1280 + i];
    {
        int i = threadIdx.x;
        int bb = bg * 32 + (i >> 3);
        usm[i] = u[(size_t)bb * FLAT + r * 8 + (i & 7)];
    }
    __syncthreads();
    for (int i = threadIdx.x; i < 5120; i += 256) {
        int bi = i / 160, ko = i - bi * 160;
        const float* wp = &Wsm[ko * 8];
        const float* up = &usm[bi * 8];
        float acc = 0.f;
        #pragma unroll
        for (int c = 0; c < 8; c++) acc += wp[c] * up[c];
        int k = ko >> 4, o = ko & 15;
        uhat[(((size_t)(bg * 32 + bi) * NCAPS + k) * ROUTES + r) * 16 + o] = acc;
    }
}

// ---------------- Routing ----------------
__global__ void zero_bij_kernel(float* __restrict__ bij) {
    int i = blockIdx.x * 256 + threadIdx.x;
    if (i < ROUTES * NCAPS) bij[i] = 0.f;
}

__global__ void softmax_routes_kernel(const float* __restrict__ b, float* __restrict__ c) {
    int k = blockIdx.x;
    __shared__ float red[256];
    int tid = threadIdx.x;
    float m = -1e30f;
    for (int r = tid; r < ROUTES; r += 256) m = fmaxf(m, b[r * 10 + k]);
    red[tid] = m; __syncthreads();
    for (int s = 128; s > 0; s >>= 1) {
        if (tid < s) red[tid] = fmaxf(red[tid], red[tid + s]);
        __syncthreads();
    }
    m = red[0]; __syncthreads();
    float sum = 0.f;
    for (int r = tid; r < ROUTES; r += 256) sum += expf(b[r * 10 + k] - m);
    red[tid] = sum; __syncthreads();
    for (int s = 128; s > 0; s >>= 1) {
        if (tid < s) red[tid] += red[tid + s];
        __syncthreads();
    }
    float inv = 1.f / red[0];
    for (int r = tid; r < ROUTES; r += 256) c[r * 10 + k] = expf(b[r * 10 + k] - m) * inv;
}

// s[b,k,:] = sum_r c[r,k]*uhat[b,k,r,:]; v = squash(s). Coalesced float4 reads.
__global__ void sv_kernel(const float* __restrict__ cij, const float* __restrict__ uhat,
                          float* __restrict__ v) {
    int b = blockIdx.x, k = blockIdx.y;
    int tid = threadIdx.x;   // 128
    __shared__ float cs[ROUTES];
    __shared__ float4 red[128];
    for (int i = tid; i < ROUTES; i += 128) cs[i] = cij[i * 10 + k];
    __syncthreads();
    const float4* base = reinterpret_cast<const float4*>(
        uhat + ((size_t)(b * NCAPS + k)) * ROUTES * 16);
    int q = tid & 3, rr = tid >> 2;
    float4 acc = make_float4(0.f, 0.f, 0.f, 0.f);
    for (int r0 = 0; r0 < ROUTES; r0 += 32) {
        int r = r0 + rr;
        float c = cs[r];
        float4 x = base[r * 4 + q];
        acc.x += c * x.x; acc.y += c * x.y; acc.z += c * x.z; acc.w += c * x.w;
    }
    red[tid] = acc; __syncthreads();
    for (int s = 64; s >= 4; s >>= 1) {
        if (tid < s) {
            float4 o = red[tid + s];
            red[tid].x += o.x; red[tid].y += o.y; red[tid].z += o.z; red[tid].w += o.w;
        }
        __syncthreads();
    }
    if (tid == 0) {
        float sv16[16]; float sn = 0.f;
        #pragma unroll
        for (int q2 = 0; q2 < 4; q2++) {
            float4 x = red[q2];
            sv16[q2*4+0] = x.x; sv16[q2*4+1] = x.y; sv16[q2*4+2] = x.z; sv16[q2*4+3] = x.w;
            sn += x.x*x.x + x.y*x.y + x.z*x.z + x.w*x.w;
        }
        float sc = sqrtf(sn) / (1.f + sn);
        #pragma unroll
        for (int o = 0; o < 16; o++) v[(b * NCAPS + k) * 16 + o] = sv16[o] * sc;
    }
}

// bij[r,k] += mean_b dot16(uhat[b,k,r,:], v[b,k,:]). Coalesced, shfl reduce over o-quads.
__global__ void agree_kernel(const float* __restrict__ uhat, const float* __restrict__ v,
                             float* __restrict__ bij) {
    int k = blockIdx.x;
    int r0 = blockIdx.y * 64;
    int tid = threadIdx.x;   // 256
    __shared__ __align__(16) float4 vs4[BATCH * 4];
    for (int i = tid; i < BATCH * 4; i += 256) {
        int b = i >> 2, q2 = i & 3;
        vs4[i] = *reinterpret_cast<const float4*>(v + (b * NCAPS + k) * 16 + q2 * 4);
    }
    __syncthreads();
    int q = tid & 3, rr = tid >> 2;  // rr 0..63
    int r = r0 + rr;
    const float4* U = reinterpret_cast<const float4*>(uhat);
    float acc = 0.f;
    for (int b = 0; b < BATCH; b++) {
        float4 x = U[((size_t)(b * NCAPS + k) * ROUTES + r) * 4 + q];
        float4 vv = vs4[b * 4 + q];
        acc += x.x*vv.x + x.y*vv.y + x.z*vv.z + x.w*vv.w;
    }
    acc += __shfl_down_sync(0xffffffffu, acc, 2);
    acc += __shfl_down_sync(0xffffffffu, acc, 1);
    if (q == 0) bij[r * 10 + k] += acc * (1.f / (float)BATCH);
}

// ---------------- Mask / argmax ----------------
__global__ void mask_kernel(const float* __restrict__ v, float* __restrict__ out_obj,
                            float* __restrict__ out_mask, int* __restrict__ best) {
    int b = blockIdx.x * blockDim.x + threadIdx.x;
    if (b >= BATCH) return;
    const float* vb = v + b * 160;
    float bestn = -1.f; int bi = 0;
    #pragma unroll
    for (int k = 0; k < 10; k++) {
        float sn = 0.f;
        #pragma unroll
        for (int o = 0; o < 16; o++) { float t = vb[k * 16 + o]; sn += t * t; }
        if (sn > bestn) { bestn = sn; bi = k; }
    }
    best[b] = bi;
    for (int i = 0; i < 160; i++) out_obj[b * 160 + i] = vb[i];
    #pragma unroll
    for (int k = 0; k < 10; k++) out_mask[b * 10 + k] = (k == bi) ? 1.f : 0.f;
}

// ---------------- Decoder ----------------
__global__ void dec1_kernel(const float* __restrict__ v, const int* __restrict__ best,
                            const float* __restrict__ w1, const float* __restrict__ b1,
                            float* __restrict__ h1) {
    int b = blockIdx.x;
    int j = threadIdx.x;
    __shared__ float vs[16];
    int bi = best[b];
    if (threadIdx.x < 16) vs[threadIdx.x] = v[b * 160 + bi * 16 + threadIdx.x];
    __syncthreads();
    float acc = b1[j];
    #pragma unroll
    for (int o = 0; o < 16; o++) acc += vs[o] * w1[(bi * 16 + o) * 512 + j];
    h1[b * 512 + j] = fmaxf(acc, 0.f);
}

template<int ACT>
__global__ void gemm_act_kernel(const float* __restrict__ A, const float* __restrict__ W,
                                const float* __restrict__ bias, float* __restrict__ C,
                                int M, int N, int K) {
    __shared__ float As[16][64];
    __shared__ float Bs[16][64];
    int tid = threadIdx.x;
    int m0 = blockIdx.y * 64, n0 = blockIdx.x * 64;
    int ty = tid >> 4, tx = tid & 15;
    float acc[4][4];
    #pragma unroll
    for (int i = 0; i < 4; i++)
        #pragma unroll
        for (int j = 0; j < 4; j++) acc[i][j] = 0.f;

    int lam = tid >> 2;
    int lak = (tid & 3) * 4;
    int lbk = tid >> 4;
    int lbn = (tid & 15) * 4;

    for (int k0 = 0; k0 < K; k0 += 16) {
        float4 av = *reinterpret_cast<const float4*>(A + (size_t)(m0 + lam) * K + k0 + lak);
        As[lak + 0][lam] = av.x; As[lak + 1][lam] = av.y;
        As[lak + 2][lam] = av.z; As[lak + 3][lam] = av.w;
        #pragma unroll
        for (int i = 0; i < 4; i++) {
            int n = n0 + lbn + i;
            Bs[lbk][lbn + i] = (n < N) ? W[(size_t)(k0 + lbk) * N + n] : 0.f;
        }
        __syncthreads();
        #pragma unroll
        for (int kk = 0; kk < 16; kk++) {
            float af[4], bf[4];
            #pragma unroll
            for (int i = 0; i < 4; i++) af[i] = As[kk][ty * 4 + i];
            #pragma unroll
            for (int j = 0; j < 4; j++) bf[j] = Bs[kk][tx * 4 + j];
            #pragma unroll
            for (int i = 0; i < 4; i++)
                #pragma unroll
                for (int j = 0; j < 4; j++)
                    acc[i][j] += af[i] * bf[j];
        }
        __syncthreads();
    }
    #pragma unroll
    for (int i = 0; i < 4; i++) {
        int m = m0 + ty * 4 + i;
        #pragma unroll
        for (int j = 0; j < 4; j++) {
            int n = n0 + tx * 4 + j;
            if (n < N) {
                float x = acc[i][j] + bias[n];
                if (ACT == 0) x = fmaxf(x, 0.f);
                else          x = 1.f / (1.f + expf(-x));
                C[(size_t)m * N + n] = x;
            }
        }
    }
}

// ---------------- Host launcher ----------------
extern "C" void kernel_launch(void* const* d_in, const int* in_sizes, int n_in,
                              void* d_out, int out_size) {
    const float* image  = (const float*)d_in[0];
    const float* conv_w = (const float*)d_in[1];
    const float* conv_b = (const float*)d_in[2];
    const float* pc_w   = (const float*)d_in[3];
    const float* pc_b   = (const float*)d_in[4];
    const float* W_obj  = (const float*)d_in[5];
    const float* dec_w1 = (const float*)d_in[6];
    const float* dec_b1 = (const float*)d_in[7];
    const float* dec_w2 = (const float*)d_in[8];
    const float* dec_b2 = (const float*)d_in[9];
    const float* dec_w3 = (const float*)d_in[10];
    const float* dec_b3 = (const float*)d_in[11];

    float* out = (float*)d_out;
    float* out_obj  = out;
    float* out_rec  = out + BATCH * 160;
    float* out_mask = out + BATCH * (160 + 784);

    unsigned char* big = nullptr; cudaGetSymbolAddress((void**)&big, g_big);
    uint32_t* aim  = (uint32_t*)big;     // live: im2col -> conv2
    float*    uhat = (float*)big;        // live: uhat_kernel onward (aim dead)
    uint32_t* x1p  = nullptr; cudaGetSymbolAddress((void**)&x1p,  g_x1p);
    uint32_t* bpp  = nullptr; cudaGetSymbolAddress((void**)&bpp,  g_bp);
    int*      koff = nullptr; cudaGetSymbolAddress((void**)&koff, g_kofft);
    float* c2   = nullptr; cudaGetSymbolAddress((void**)&c2,   g_c2);
    float* u    = nullptr; cudaGetSymbolAddress((void**)&u,    g_u);
    float* bij  = nullptr; cudaGetSymbolAddress((void**)&bij,  g_bij);
    float* cij  = nullptr; cudaGetSymbolAddress((void**)&cij,  g_cij);
    float* v    = nullptr; cudaGetSymbolAddress((void**)&v,    g_v);
    int*   best = nullptr; cudaGetSymbolAddress((void**)&best, g_best);
    float* h1   = nullptr; cudaGetSymbolAddress((void**)&h1,   g_h1);
    float* h2   = nullptr; cudaGetSymbolAddress((void**)&h2,   g_h2);

    // 0) pre-split B + offset table
    bsplit_kernel<<<(N2 * K2 + 1023) / 1024, 1024>>>(pc_w, bpp);
    kofft_kernel<<<(K2 + 255) / 256, 256>>>(koff);
    // 1) conv1 + relu -> packed bf16 split
    conv1_kernel<<<dim3(BATCH, 8), 256>>>(image, conv_w, conv_b, x1p);
    // 2) im2col materialization
    im2col_kernel<<<M2, 256>>>(x1p, koff, aim);
    // 3) conv2: dense split-bf16 MMA GEMM
    conv2_mma_kernel<<<dim3(N2 / 128, M2 / 128), 512>>>(aim, bpp, pc_b, c2);
    // 4) squash -> u
    squash_u_kernel<<<(BATCH * ROUTES + 255) / 256, 256>>>(c2, u);
    // 5) u_hat ([b][k][r][o]) — reuses big buffer (aim dead now)
    uhat_kernel<<<dim3(ROUTES, BATCH / 32), 256>>>(W_obj, u, uhat);
    // 6) routing (3 iterations)
    zero_bij_kernel<<<(ROUTES * NCAPS + 255) / 256, 256>>>(bij);
    for (int it = 0; it < 3; it++) {
        softmax_routes_kernel<<<NCAPS, 256>>>(bij, cij);
        sv_kernel<<<dim3(BATCH, NCAPS), 128>>>(cij, uhat, v);
        if (it < 2)
            agree_kernel<<<dim3(NCAPS, ROUTES / 64), 256>>>(uhat, v, bij);
    }
    // 7) mask + obj output
    mask_kernel<<<2, 256>>>(v, out_obj, out_mask, best);
    // 8) decoder
    dec1_kernel<<<BATCH, 512>>>(v, best, dec_w1, dec_b1, h1);
    gemm_act_kernel<0><<<dim3(1024 / 64, BATCH / 64), 256>>>(h1, dec_w2, dec_b2, h2, BATCH, 1024, 512);
    gemm_act_kernel<1><<<dim3((784 + 63) / 64, BATCH / 64), 256>>>(h2, dec_w3, dec_b3, out_rec, BATCH, 784, 1024);
}